// round 2
// baseline (speedup 1.0000x reference)
#include <cuda_runtime.h>
#include <stdint.h>

// dice_shape_loss: mean over 64*1*448*448 = 12,845,056 elements of
//   a = -(y*max(log p,-100) + (1-y)*max(log(1-p),-100));  out = mean(a*(1+shapeloss))
// HBM-bound streaming reduction: 154.1 MB read, 4 B write.

#define LOG_CLAMP (-100.0f)

__global__ void zero_out_kernel(float* out) {
    if (threadIdx.x == 0) out[0] = 0.0f;
}

__device__ __forceinline__ float elem_loss(float t, float p, float s) {
    float lp = fmaxf(__logf(p), LOG_CLAMP);
    float lq = fmaxf(__logf(1.0f - p), LOG_CLAMP);
    // a = -(t*lp + (1-t)*lq)   (t is exactly 0.0 or 1.0)
    float a = -fmaf(t, lp - lq, lq);
    return fmaf(a, s, a);   // a*s + a
}

__device__ __forceinline__ float quad_loss(float4 t, float4 p, float4 s) {
    float acc;
    acc  = elem_loss(t.x, p.x, s.x);
    acc += elem_loss(t.y, p.y, s.y);
    acc += elem_loss(t.z, p.z, s.z);
    acc += elem_loss(t.w, p.w, s.w);
    return acc;
}

__global__ void __launch_bounds__(256)
bce_shape_reduce_kernel(const float4* __restrict__ yt,
                        const float4* __restrict__ yp,
                        const float4* __restrict__ sl,
                        float* __restrict__ out,
                        int n4, float inv_n) {
    float acc = 0.0f;
    int idx    = blockIdx.x * blockDim.x + threadIdx.x;
    int stride = gridDim.x * blockDim.x;

    // 2-deep batch: 6 independent LDG.128 issued before any compute consumes
    // them -> high MLP_p1, saturates LTS/DRAM path.
    int i = idx;
    for (; i + stride < n4; i += 2 * stride) {
        float4 t0 = yt[i];
        float4 p0 = yp[i];
        float4 s0 = sl[i];
        float4 t1 = yt[i + stride];
        float4 p1 = yp[i + stride];
        float4 s1 = sl[i + stride];
        acc += quad_loss(t0, p0, s0);
        acc += quad_loss(t1, p1, s1);
    }
    if (i < n4) {
        acc += quad_loss(yt[i], yp[i], sl[i]);
    }

    // warp reduce
    #pragma unroll
    for (int o = 16; o > 0; o >>= 1)
        acc += __shfl_down_sync(0xFFFFFFFFu, acc, o);

    __shared__ float warp_sums[8];
    int lane = threadIdx.x & 31;
    int wid  = threadIdx.x >> 5;
    if (lane == 0) warp_sums[wid] = acc;
    __syncthreads();

    if (wid == 0) {
        float v = (lane < (blockDim.x >> 5)) ? warp_sums[lane] : 0.0f;
        #pragma unroll
        for (int o = 4; o > 0; o >>= 1)
            v += __shfl_down_sync(0xFFFFFFFFu, v, o);
        if (lane == 0)
            atomicAdd(out, v * inv_n);
    }
}

extern "C" void kernel_launch(void* const* d_in, const int* in_sizes, int n_in,
                              void* d_out, int out_size) {
    const float4* yt = (const float4*)d_in[0];  // y_true
    const float4* yp = (const float4*)d_in[1];  // y_pred
    const float4* sl = (const float4*)d_in[2];  // shapeloss
    float* out = (float*)d_out;

    int n  = in_sizes[0];            // 12,845,056
    int n4 = n >> 2;                 // 3,211,264 (divisible by 4)
    float inv_n = 1.0f / (float)n;

    zero_out_kernel<<<1, 32>>>(out);

    // 148 SMs x 8 CTAs of 256 threads: single perfectly-balanced wave,
    // ~10.6 float4-triples per thread in the grid-stride loop.
    const int threads = 256;
    const int blocks  = 148 * 8;
    bce_shape_reduce_kernel<<<blocks, threads>>>(yt, yp, sl, out, n4, inv_n);
}